// round 1
// baseline (speedup 1.0000x reference)
#include <cuda_runtime.h>

// Problem constants (from metadata: x[16,128,8192] f32, weights1[128,128,2048] f32,
// output [16,128,4097] f32).
#define B_    16
#define CIN_  128
#define COUT_ 128
#define N_    8192
#define MODES_ 2048
#define LOUT_ 4097

// Row sums S[b,i] = sum_n x[b,i,n]
__device__ float g_S[B_ * CIN_];

// ---------------------------------------------------------------------------
// Kernel 1: per-row sum of x. 2048 rows of 8192 floats. float4 loads, fully
// coalesced; warp shuffle + smem block reduction.
// ---------------------------------------------------------------------------
__global__ void __launch_bounds__(256) rowsum_kernel(const float* __restrict__ x) {
    const int row = blockIdx.x;                       // 0..2047  (= b*128 + i)
    const float4* __restrict__ xr =
        reinterpret_cast<const float4*>(x) + (size_t)row * (N_ / 4);

    float sum = 0.0f;
    // 8192/4 = 2048 float4 per row; 256 threads -> 8 each, unrolled for MLP.
    #pragma unroll
    for (int j = 0; j < (N_ / 4) / 256; j++) {
        float4 v = xr[threadIdx.x + j * 256];
        sum += (v.x + v.y) + (v.z + v.w);
    }

    // warp reduction
    #pragma unroll
    for (int off = 16; off > 0; off >>= 1)
        sum += __shfl_xor_sync(0xffffffffu, sum, off);

    __shared__ float wsum[8];
    const int lane = threadIdx.x & 31;
    const int wid  = threadIdx.x >> 5;
    if (lane == 0) wsum[wid] = sum;
    __syncthreads();

    if (wid == 0) {
        float s = (lane < 8) ? wsum[lane] : 0.0f;
        #pragma unroll
        for (int off = 4; off > 0; off >>= 1)
            s += __shfl_xor_sync(0xffffffffu, s, off);
        if (lane == 0) g_S[row] = s;
    }
}

// ---------------------------------------------------------------------------
// Kernel 2: zero-fill the entire output (reference output is 0 everywhere
// except column 0 of the last axis). out_size = 16*128*4097 floats, divisible
// by 4 -> float4 grid-stride stores.
// ---------------------------------------------------------------------------
__global__ void __launch_bounds__(256) zero_kernel(float4* __restrict__ out, int n4) {
    int idx = blockIdx.x * blockDim.x + threadIdx.x;
    int stride = gridDim.x * blockDim.x;
    float4 z = make_float4(0.0f, 0.0f, 0.0f, 0.0f);
    for (int i = idx; i < n4; i += stride) out[i] = z;
}

// ---------------------------------------------------------------------------
// Kernel 3: the 2048 nonzero outputs.
//   out[b,o,0] = (1/4097) * sum_i S[b,i] * w[i,o,0]
// w layout [CIN][COUT][MODES] -> w[(i*COUT+o)*MODES]. 16 blocks (one per b),
// 128 threads (one per o). w column-0 reads are strided (1 float per sector)
// but total only ~16K loads — negligible.
// ---------------------------------------------------------------------------
__global__ void __launch_bounds__(128) head_kernel(const float* __restrict__ w,
                                                   float* __restrict__ out) {
    const int b = blockIdx.x;
    const int o = threadIdx.x;

    __shared__ float Ssh[CIN_];
    Ssh[o] = g_S[b * CIN_ + o];   // CIN_ == blockDim.x == 128
    __syncthreads();

    float acc = 0.0f;
    #pragma unroll 8
    for (int i = 0; i < CIN_; i++) {
        acc += Ssh[i] * __ldg(&w[(size_t)(i * COUT_ + o) * MODES_]);
    }
    out[(size_t)(b * COUT_ + o) * LOUT_] = acc * (1.0f / 4097.0f);
}

// ---------------------------------------------------------------------------
extern "C" void kernel_launch(void* const* d_in, const int* in_sizes, int n_in,
                              void* d_out, int out_size) {
    const float* x = (const float*)d_in[0];
    const float* w = (const float*)d_in[1];
    float* out = (float*)d_out;

    // 1) row sums of x
    rowsum_kernel<<<B_ * CIN_, 256>>>(x);

    // 2) zero-fill output
    int n4 = out_size / 4;   // 8390656 / 4 = 2097664
    zero_kernel<<<4096, 256>>>((float4*)out, n4);

    // 3) write the 2048 nonzero entries (after zero-fill on same stream)
    head_kernel<<<B_, 128>>>(w, out);
}

// round 2
// speedup vs baseline: 1.7317x; 1.7317x over previous
#include <cuda_runtime.h>

// Problem constants: x[16,128,8192] f32, weights1[128,128,2048] f32,
// output [16,128,4097] f32.
#define B_     16
#define CIN_   128
#define COUT_  128
#define N_     8192
#define MODES_ 2048
#define LOUT_  4097

#define NROWS  (B_ * CIN_)            // 2048
#define OUT4   ((B_ * COUT_ * LOUT_) / 4)   // 2097664 float4
#define OUT4_PER_BLK (OUT4 / NROWS)   // 1024

// Row sums S[b,i] = sum_n x[b,i,n]
__device__ float g_S[NROWS];
// Gathered first-mode weights, contiguous: g_W[i*COUT_ + o] = w[i,o,0]
__device__ float g_W[CIN_ * COUT_];

// ---------------------------------------------------------------------------
// Fused kernel: per block (one per x-row):
//   (a) zero-store its 1024-float4 slice of out (fire-and-forget),
//   (b) blocks 0..127 additionally gather w[i, o, 0] -> g_W (1 load/thread),
//   (c) reduce its 8192-float row of x with streaming loads.
// ---------------------------------------------------------------------------
__global__ void __launch_bounds__(256) fused_kernel(const float* __restrict__ x,
                                                    const float* __restrict__ w,
                                                    float4* __restrict__ out) {
    const int row = blockIdx.x;            // 0..2047
    const int tid = threadIdx.x;

    // (a) zero slice of out — independent stores, overlap with everything
    {
        float4 z = make_float4(0.0f, 0.0f, 0.0f, 0.0f);
        float4* o = out + (size_t)row * OUT4_PER_BLK;
        #pragma unroll
        for (int j = 0; j < OUT4_PER_BLK / 256; j++)
            o[tid + j * 256] = z;
    }

    // (b) gather weight column 0: block i (<128), threads 0..127, one load each
    if (row < CIN_ && tid < COUT_) {
        g_W[row * COUT_ + tid] = __ldg(&w[(size_t)(row * COUT_ + tid) * MODES_]);
    }

    // (c) row sum with streaming (evict-first) float4 loads, 8-deep MLP
    const float4* __restrict__ xr =
        reinterpret_cast<const float4*>(x) + (size_t)row * (N_ / 4);
    float sum = 0.0f;
    #pragma unroll
    for (int j = 0; j < (N_ / 4) / 256; j++) {
        float4 v = __ldcs(&xr[tid + j * 256]);
        sum += (v.x + v.y) + (v.z + v.w);
    }

    // warp + block reduction
    #pragma unroll
    for (int off = 16; off > 0; off >>= 1)
        sum += __shfl_xor_sync(0xffffffffu, sum, off);

    __shared__ float wsum[8];
    const int lane = tid & 31;
    const int wid  = tid >> 5;
    if (lane == 0) wsum[wid] = sum;
    __syncthreads();
    if (wid == 0) {
        float s = (lane < 8) ? wsum[lane] : 0.0f;
        #pragma unroll
        for (int off = 4; off > 0; off >>= 1)
            s += __shfl_xor_sync(0xffffffffu, s, off);
        if (lane == 0) g_S[row] = s;
    }
}

// ---------------------------------------------------------------------------
// Head kernel: out[b,o,0] = (1/4097) * sum_i S[b,i] * g_W[i*128+o]
// 16 blocks (one per b), 128 threads (one per o). All reads contiguous now.
// ---------------------------------------------------------------------------
__global__ void __launch_bounds__(128) head_kernel(float* __restrict__ out) {
    const int b = blockIdx.x;
    const int o = threadIdx.x;

    __shared__ float Ssh[CIN_];
    Ssh[o] = g_S[b * CIN_ + o];
    __syncthreads();

    float acc = 0.0f;
    #pragma unroll 16
    for (int i = 0; i < CIN_; i++) {
        acc += Ssh[i] * g_W[i * COUT_ + o];   // coalesced across o
    }
    out[(size_t)(b * COUT_ + o) * LOUT_] = acc * (1.0f / 4097.0f);
}

// ---------------------------------------------------------------------------
extern "C" void kernel_launch(void* const* d_in, const int* in_sizes, int n_in,
                              void* d_out, int out_size) {
    const float* x = (const float*)d_in[0];
    const float* w = (const float*)d_in[1];
    float* out = (float*)d_out;

    fused_kernel<<<NROWS, 256>>>(x, w, (float4*)out);
    head_kernel<<<B_, 128>>>(out);
}